// round 14
// baseline (speedup 1.0000x reference)
#include <cuda_runtime.h>
#include <cuda_bf16.h>
#include <math.h>
#include <stdint.h>

// ----------------------------------------------------------------------------
// Problem constants
// ----------------------------------------------------------------------------
#define BATCH   2
#define SEQ     2048
#define TOK     (BATCH * SEQ)        // 4096 rows
#define DMODEL  1024
#define DFF     4096
#define NHEADS  16
#define HDIM    64
#define LN_EPS  1e-5f
#define QSCALE  (0.125f * 1.44269504f)

// ----------------------------------------------------------------------------
// Scratch buffers
// ----------------------------------------------------------------------------
__device__ uint16_t h_q [TOK * DMODEL];   // fp16 Q (pre-scaled by QSCALE)
__device__ uint16_t h_k [TOK * DMODEL];   // fp16 K
__device__ uint16_t h_v [TOK * DMODEL];   // fp16 V
__device__ float g_attn[TOK * DMODEL];
__device__ float g_tmp [TOK * DMODEL];
__device__ float g_y1  [TOK * DMODEL];
__device__ float g_y2  [TOK * DMODEL];
__device__ float g_ffn [TOK * DFF];

// pack two fp32 -> bf16x2 / f16x2 (first asm src -> HIGH half)
__device__ __forceinline__ uint32_t packbf(float lo, float hi) {
    uint32_t d;
    asm("cvt.rn.bf16x2.f32 %0, %1, %2;" : "=r"(d) : "f"(hi), "f"(lo));
    return d;
}
__device__ __forceinline__ uint32_t packh(float lo, float hi) {
    uint32_t d;
    asm("cvt.rn.f16x2.f32 %0, %1, %2;" : "=r"(d) : "f"(hi), "f"(lo));
    return d;
}
__device__ __forceinline__ uint32_t ex2h2(uint32_t x) {
    uint32_t r;
    asm("ex2.approx.f16x2 %0, %1;" : "=r"(r) : "r"(x));
    return r;
}
__device__ __forceinline__ uint32_t smem_u32(const void* p) {
    return (uint32_t)__cvta_generic_to_shared(p);
}

#define MMA_BF16(acc, a, b0v, b1v)                                         \
    asm volatile(                                                          \
        "mma.sync.aligned.m16n8k16.row.col.f32.bf16.bf16.f32 "             \
        "{%0,%1,%2,%3}, {%4,%5,%6,%7}, {%8,%9}, {%0,%1,%2,%3};"            \
        : "+f"((acc)[0]), "+f"((acc)[1]), "+f"((acc)[2]), "+f"((acc)[3])   \
        : "r"((a)[0]), "r"((a)[1]), "r"((a)[2]), "r"((a)[3]),              \
          "r"(b0v), "r"(b1v))

#define MMA_F16(acc, a, b0v, b1v)                                          \
    asm volatile(                                                          \
        "mma.sync.aligned.m16n8k16.row.col.f32.f16.f16.f32 "               \
        "{%0,%1,%2,%3}, {%4,%5,%6,%7}, {%8,%9}, {%0,%1,%2,%3};"            \
        : "+f"((acc)[0]), "+f"((acc)[1]), "+f"((acc)[2]), "+f"((acc)[3])   \
        : "r"((a)[0]), "r"((a)[1]), "r"((a)[2]), "r"((a)[3]),              \
          "r"(b0v), "r"(b1v))

#define LDSM_X4_TRANS(r0, r1, r2, r3, addr)                                \
    asm volatile(                                                          \
        "ldmatrix.sync.aligned.m8n8.x4.trans.shared.b16 "                  \
        "{%0,%1,%2,%3}, [%4];"                                             \
        : "=r"(r0), "=r"(r1), "=r"(r2), "=r"(r3) : "r"(addr))

// ----------------------------------------------------------------------------
// Shared GEMM mainloop bits (R8-validated layout)
// ----------------------------------------------------------------------------
#define A_WSTR 12
#define B_WSTR 136
#define A_WRDS (128 * A_WSTR)
#define B_WRDS (8 * B_WSTR)

// ----------------------------------------------------------------------------
// bf16 GEMM with fp32 output (+bias, +residual, ReLU) — unchanged from R8.
// ----------------------------------------------------------------------------
struct GemmArgs {
    const float* A[3];
    const float* W[3];
    const float* bias[3];
    const float* R[3];
    float*       C[3];
    int N, K;
};

template<bool RELU, bool RES>
__global__ __launch_bounds__(256, 2) void gemm_bf16(GemmArgs args)
{
    __shared__ uint32_t As[2][A_WRDS];
    __shared__ uint32_t Bs[2][B_WRDS];

    const int zi = blockIdx.z;
    const float* __restrict__ A    = args.A[zi];
    const float* __restrict__ W    = args.W[zi];
    const float* __restrict__ bias = args.bias[zi];
    const float* __restrict__ Rp   = args.R[zi];
    float*       __restrict__ C    = args.C[zi];
    const int N = args.N, K = args.K;

    const int tid  = threadIdx.x;
    const int lane = tid & 31;
    const int warp = tid >> 5;
    const int g    = lane >> 2;
    const int tg   = lane & 3;
    const int wm   = (warp >> 2) * 64;
    const int wn   = (warp & 3) * 32;
    const int bm   = blockIdx.y * 128;
    const int bn   = blockIdx.x * 128;

    const int a_row = tid >> 2;
    const int a_c4  = (tid & 3) * 4;
    const int b_p   = tid >> 5;
    const int b_c4  = (tid & 31) * 4;

    const float* Ag0 = A + (size_t)(bm + a_row)      * K + a_c4;
    const float* Ag1 = A + (size_t)(bm + a_row + 64) * K + a_c4;
    const float* Wg0 = W + (size_t)(2 * b_p)     * N + bn + b_c4;
    const float* Wg1 = W + (size_t)(2 * b_p + 1) * N + bn + b_c4;

    float acc[4][4][4];
#pragma unroll
    for (int i = 0; i < 4; i++)
#pragma unroll
        for (int j = 0; j < 4; j++)
#pragma unroll
            for (int r = 0; r < 4; r++) acc[i][j][r] = 0.f;

    float4 ra0, ra1, rb0, rb1;

#define LOADG(t) do {                                                \
        const size_t ka = (size_t)(t) * 16;                          \
        const size_t kb = (size_t)(t) * 16 * (size_t)N;              \
        ra0 = *(const float4*)(Ag0 + ka);                            \
        ra1 = *(const float4*)(Ag1 + ka);                            \
        rb0 = *(const float4*)(Wg0 + kb);                            \
        rb1 = *(const float4*)(Wg1 + kb);                            \
    } while (0)

#define STORES(buf) do {                                             \
        uint32_t* as_ = As[buf];                                     \
        uint32_t* bs_ = Bs[buf];                                     \
        uint2 aw0, aw1;                                              \
        aw0.x = packbf(ra0.x, ra0.y); aw0.y = packbf(ra0.z, ra0.w);  \
        aw1.x = packbf(ra1.x, ra1.y); aw1.y = packbf(ra1.z, ra1.w);  \
        *(uint2*)(as_ + a_row * A_WSTR + (a_c4 >> 1)) = aw0;         \
        *(uint2*)(as_ + (a_row + 64) * A_WSTR + (a_c4 >> 1)) = aw1;  \
        uint4 bw;                                                    \
        bw.x = packbf(rb0.x, rb1.x); bw.y = packbf(rb0.y, rb1.y);    \
        bw.z = packbf(rb0.z, rb1.z); bw.w = packbf(rb0.w, rb1.w);    \
        *(uint4*)(bs_ + b_p * B_WSTR + b_c4) = bw;                   \
    } while (0)

    const int NT = K >> 4;

    LOADG(0);
    STORES(0);
    __syncthreads();

    for (int t = 0; t < NT; t++) {
        const int cur = t & 1;
        if (t + 1 < NT) LOADG(t + 1);

        const uint32_t* as_ = As[cur];
        const uint32_t* bs_ = Bs[cur];

        unsigned af[4][4], bf2[4][2];
#pragma unroll
        for (int mt = 0; mt < 4; mt++) {
            const uint32_t* ap = as_ + (wm + mt * 16 + g) * A_WSTR + tg;
            af[mt][0] = ap[0];
            af[mt][1] = ap[8 * A_WSTR];
            af[mt][2] = ap[4];
            af[mt][3] = ap[8 * A_WSTR + 4];
        }
#pragma unroll
        for (int nt = 0; nt < 4; nt++) {
            const int col = wn + nt * 8 + g;
            bf2[nt][0] = bs_[tg * B_WSTR + col];
            bf2[nt][1] = bs_[(tg + 4) * B_WSTR + col];
        }
#pragma unroll
        for (int mt = 0; mt < 4; mt++)
#pragma unroll
            for (int nt = 0; nt < 4; nt++)
                MMA_BF16(acc[mt][nt], af[mt], bf2[nt][0], bf2[nt][1]);

        if (t + 1 < NT) STORES((t + 1) & 1);
        __syncthreads();
    }

#pragma unroll
    for (int mt = 0; mt < 4; mt++) {
        const int row0 = bm + wm + mt * 16 + g;
#pragma unroll
        for (int nt = 0; nt < 4; nt++) {
            const int col = bn + wn + nt * 8 + tg * 2;
            const float bv0 = bias[col], bv1 = bias[col + 1];
            float2 v0, v1;
            v0.x = acc[mt][nt][0] + bv0; v0.y = acc[mt][nt][1] + bv1;
            v1.x = acc[mt][nt][2] + bv0; v1.y = acc[mt][nt][3] + bv1;
            if (RES) {
                float2 r0 = *(const float2*)(Rp + (size_t)row0 * N + col);
                float2 r1 = *(const float2*)(Rp + (size_t)(row0 + 8) * N + col);
                v0.x += r0.x; v0.y += r0.y;
                v1.x += r1.x; v1.y += r1.y;
            }
            if (RELU) {
                v0.x = fmaxf(v0.x, 0.f); v0.y = fmaxf(v0.y, 0.f);
                v1.x = fmaxf(v1.x, 0.f); v1.y = fmaxf(v1.y, 0.f);
            }
            *(float2*)(C + (size_t)row0 * N + col)       = v0;
            *(float2*)(C + (size_t)(row0 + 8) * N + col) = v1;
        }
    }
#undef LOADG
#undef STORES
}

// ----------------------------------------------------------------------------
// bf16 GEMM with fp16 output: C16 = f16((A@W + bias) * scale).
// ----------------------------------------------------------------------------
struct GemmH16Args {
    const float* A[3];
    const float* W[3];
    const float* bias[3];
    uint16_t*    C[3];
    float        scale[3];
    int N, K;
};

__global__ __launch_bounds__(256, 2) void gemm_h16(GemmH16Args args)
{
    __shared__ uint32_t As[2][A_WRDS];
    __shared__ uint32_t Bs[2][B_WRDS];

    const int zi = blockIdx.z;
    const float* __restrict__ A    = args.A[zi];
    const float* __restrict__ W    = args.W[zi];
    const float* __restrict__ bias = args.bias[zi];
    uint16_t*    __restrict__ C16  = args.C[zi];
    const float sc = args.scale[zi];
    const int N = args.N, K = args.K;

    const int tid  = threadIdx.x;
    const int lane = tid & 31;
    const int warp = tid >> 5;
    const int g    = lane >> 2;
    const int tg   = lane & 3;
    const int wm   = (warp >> 2) * 64;
    const int wn   = (warp & 3) * 32;
    const int bm   = blockIdx.y * 128;
    const int bn   = blockIdx.x * 128;

    const int a_row = tid >> 2;
    const int a_c4  = (tid & 3) * 4;
    const int b_p   = tid >> 5;
    const int b_c4  = (tid & 31) * 4;

    const float* Ag0 = A + (size_t)(bm + a_row)      * K + a_c4;
    const float* Ag1 = A + (size_t)(bm + a_row + 64) * K + a_c4;
    const float* Wg0 = W + (size_t)(2 * b_p)     * N + bn + b_c4;
    const float* Wg1 = W + (size_t)(2 * b_p + 1) * N + bn + b_c4;

    float acc[4][4][4];
#pragma unroll
    for (int i = 0; i < 4; i++)
#pragma unroll
        for (int j = 0; j < 4; j++)
#pragma unroll
            for (int r = 0; r < 4; r++) acc[i][j][r] = 0.f;

    float4 ra0, ra1, rb0, rb1;

#define LOADG(t) do {                                                \
        const size_t ka = (size_t)(t) * 16;                          \
        const size_t kb = (size_t)(t) * 16 * (size_t)N;              \
        ra0 = *(const float4*)(Ag0 + ka);                            \
        ra1 = *(const float4*)(Ag1 + ka);                            \
        rb0 = *(const float4*)(Wg0 + kb);                            \
        rb1 = *(const float4*)(Wg1 + kb);                            \
    } while (0)

#define STORES(buf) do {                                             \
        uint32_t* as_ = As[buf];                                     \
        uint32_t* bs_ = Bs[buf];                                     \
        uint2 aw0, aw1;                                              \
        aw0.x = packbf(ra0.x, ra0.y); aw0.y = packbf(ra0.z, ra0.w);  \
        aw1.x = packbf(ra1.x, ra1.y); aw1.y = packbf(ra1.z, ra1.w);  \
        *(uint2*)(as_ + a_row * A_WSTR + (a_c4 >> 1)) = aw0;         \
        *(uint2*)(as_ + (a_row + 64) * A_WSTR + (a_c4 >> 1)) = aw1;  \
        uint4 bw;                                                    \
        bw.x = packbf(rb0.x, rb1.x); bw.y = packbf(rb0.y, rb1.y);    \
        bw.z = packbf(rb0.z, rb1.z); bw.w = packbf(rb0.w, rb1.w);    \
        *(uint4*)(bs_ + b_p * B_WSTR + b_c4) = bw;                   \
    } while (0)

    const int NT = K >> 4;

    LOADG(0);
    STORES(0);
    __syncthreads();

    for (int t = 0; t < NT; t++) {
        const int cur = t & 1;
        if (t + 1 < NT) LOADG(t + 1);

        const uint32_t* as_ = As[cur];
        const uint32_t* bs_ = Bs[cur];

        unsigned af[4][4], bf2[4][2];
#pragma unroll
        for (int mt = 0; mt < 4; mt++) {
            const uint32_t* ap = as_ + (wm + mt * 16 + g) * A_WSTR + tg;
            af[mt][0] = ap[0];
            af[mt][1] = ap[8 * A_WSTR];
            af[mt][2] = ap[4];
            af[mt][3] = ap[8 * A_WSTR + 4];
        }
#pragma unroll
        for (int nt = 0; nt < 4; nt++) {
            const int col = wn + nt * 8 + g;
            bf2[nt][0] = bs_[tg * B_WSTR + col];
            bf2[nt][1] = bs_[(tg + 4) * B_WSTR + col];
        }
#pragma unroll
        for (int mt = 0; mt < 4; mt++)
#pragma unroll
            for (int nt = 0; nt < 4; nt++)
                MMA_BF16(acc[mt][nt], af[mt], bf2[nt][0], bf2[nt][1]);

        if (t + 1 < NT) STORES((t + 1) & 1);
        __syncthreads();
    }

#pragma unroll
    for (int mt = 0; mt < 4; mt++) {
        const int row0 = bm + wm + mt * 16 + g;
#pragma unroll
        for (int nt = 0; nt < 4; nt++) {
            const int col = bn + wn + nt * 8 + tg * 2;
            const float bv0 = bias[col], bv1 = bias[col + 1];
            const uint32_t w0 = packh((acc[mt][nt][0] + bv0) * sc,
                                      (acc[mt][nt][1] + bv1) * sc);
            const uint32_t w1 = packh((acc[mt][nt][2] + bv0) * sc,
                                      (acc[mt][nt][3] + bv1) * sc);
            *(uint32_t*)(C16 + (size_t)row0 * N + col)       = w0;
            *(uint32_t*)(C16 + (size_t)(row0 + 8) * N + col) = w1;
        }
    }
#undef LOADG
#undef STORES
}

// ----------------------------------------------------------------------------
// fp16 flash attention, 128-row q-tile (8 warps). Per-warp math identical
// to the R12/R13-validated 4-warp version; each staged KV tile now serves
// 128 q rows (staging traffic and barrier count halved).
// ----------------------------------------------------------------------------
#define HSTR 72            // halves per smem row (64 + 8 pad)

template<bool CAUSAL>
__global__ __launch_bounds__(256) void attn_fp16(
    const uint16_t* __restrict__ Q, const uint16_t* __restrict__ K,
    const uint16_t* __restrict__ V, float* __restrict__ O)
{
    __shared__ __align__(16) uint16_t sQ[128 * HSTR];
    __shared__ __align__(16) uint16_t sK[64 * HSTR];
    __shared__ __align__(16) uint16_t sV[64 * HSTR];
    uint32_t* sQw = (uint32_t*)sQ;     // word stride 36
    uint32_t* sKw = (uint32_t*)sK;

    const int b  = blockIdx.z;
    const int h  = blockIdx.y;
    const int q0 = blockIdx.x * 128;
    const int tid  = threadIdx.x;
    const int lane = tid & 31;
    const int w    = tid >> 5;          // 0..7
    const int g    = lane >> 2;
    const int tg   = lane & 3;
    const size_t hoff = ((size_t)(b * NHEADS + h)) * SEQ * HDIM;
    const uint32_t sVbase = smem_u32(sV);

    // ---- stage Q: 128 rows x 8 uint4 = 1024 copies, 4/thread ----
#pragma unroll
    for (int i = 0; i < 4; i++) {
        const int idx = tid + i * 256;
        const int row = idx >> 3;
        const int c8  = idx & 7;
        uint4 qv = *(const uint4*)(Q + hoff + (size_t)(q0 + row) * HDIM + c8 * 8);
        *(uint4*)(sQw + row * 36 + c8 * 4) = qv;
    }
    __syncthreads();

    // ---- Q fragments (register resident); rows = w*16 + {g, g+8} ----
    uint32_t aQ[4][4];
#pragma unroll
    for (int kk = 0; kk < 4; kk++) {
        const uint32_t* qb = sQw + (w * 16 + g) * 36 + kk * 8 + tg;
        aQ[kk][0] = qb[0];
        aQ[kk][1] = qb[8 * 36];
        aQ[kk][2] = qb[4];
        aQ[kk][3] = qb[8 * 36 + 4];
    }

    float cO[8][4];
#pragma unroll
    for (int nt = 0; nt < 8; nt++)
#pragma unroll
        for (int r = 0; r < 4; r++) cO[nt][r] = 0.f;
    float lrow[2] = { 0.f, 0.f };

    const int ntiles = CAUSAL ? (q0 / 64 + 2) : (SEQ / 64);

    for (int t = 0; t < ntiles; t++) {
        const int j0 = t * 64;
        __syncthreads();
        // ---- stage K, V: 64 rows x 8 uint4 = 512 copies, 2/thread ----
#pragma unroll
        for (int i = 0; i < 2; i++) {
            const int idx = tid + i * 256;
            const int row = idx >> 3;
            const int c8  = idx & 7;
            const size_t gaddr = hoff + (size_t)(j0 + row) * HDIM + c8 * 8;
            uint4 kv = *(const uint4*)(K + gaddr);
            *(uint4*)(sKw + row * 36 + c8 * 4) = kv;
            uint4 vv = *(const uint4*)(V + gaddr);
            *(uint4*)((uint32_t*)sV + row * 36 + c8 * 4) = vv;
        }
        __syncthreads();

        // ---- S = Q @ K^T (log2 domain; scale pre-folded into Q) ----
        float cS[8][4];
#pragma unroll
        for (int nt = 0; nt < 8; nt++)
#pragma unroll
            for (int r = 0; r < 4; r++) cS[nt][r] = 0.f;

#pragma unroll
        for (int kk = 0; kk < 4; kk++)
#pragma unroll
            for (int nt = 0; nt < 8; nt++) {
                const uint32_t* kp = sKw + (nt * 8 + g) * 36 + kk * 8 + tg;
                MMA_F16(cS[nt], aQ[kk], kp[0], kp[4]);
            }

        // ---- causal mask (last two tiles overlap the diagonal band) ----
        if (CAUSAL && t >= ntiles - 2) {
            const int rbase = q0 + w * 16 + g;
#pragma unroll
            for (int nt = 0; nt < 8; nt++) {
                const int c0 = j0 + nt * 8 + tg * 2;
                if (c0     > rbase)     cS[nt][0] = -1e30f;
                if (c0 + 1 > rbase)     cS[nt][1] = -1e30f;
                if (c0     > rbase + 8) cS[nt][2] = -1e30f;
                if (c0 + 1 > rbase + 8) cS[nt][3] = -1e30f;
            }
        }

        // ---- p = 2^S, packed f16x2 (these ARE the PV A-frag words) ----
        uint32_t plo[8], phi[8];
#pragma unroll
        for (int nt = 0; nt < 8; nt++) {
            plo[nt] = ex2h2(packh(cS[nt][0], cS[nt][1]));
            phi[nt] = ex2h2(packh(cS[nt][2], cS[nt][3]));
        }

        uint32_t aP[4][4];
#pragma unroll
        for (int kk = 0; kk < 4; kk++) {
            aP[kk][0] = plo[2 * kk];
            aP[kk][1] = phi[2 * kk];
            aP[kk][2] = plo[2 * kk + 1];
            aP[kk][3] = phi[2 * kk + 1];
        }

        // ---- row sums via mma with B = ones (fp32 accumulate) ----
        {
            float cSum[4] = { 0.f, 0.f, 0.f, 0.f };
#pragma unroll
            for (int kk = 0; kk < 4; kk++)
                MMA_F16(cSum, aP[kk], 0x3C003C00u, 0x3C003C00u);
            lrow[0] += cSum[0];
            lrow[1] += cSum[2];
        }

        // ---- O += P @ V : V B-frags via ldmatrix.x4.trans ----
#pragma unroll
        for (int kk = 0; kk < 4; kk++)
#pragma unroll
            for (int np = 0; np < 4; np++) {
                const int mat = lane >> 3;
                const int r   = lane & 7;
                const int key = kk * 16 + (mat & 1) * 8 + r;
                const int dcl = np * 16 + (mat >> 1) * 8;
                const uint32_t addr = sVbase + (uint32_t)(key * HSTR + dcl) * 2;
                uint32_t v0, v1, v2, v3;
                LDSM_X4_TRANS(v0, v1, v2, v3, addr);
                MMA_F16(cO[2 * np],     aP[kk], v0, v1);
                MMA_F16(cO[2 * np + 1], aP[kk], v2, v3);
            }
    }

    // ---- epilogue: normalize and store (folds head transpose) ----
    const float inv0 = 1.f / lrow[0];
    const float inv1 = 1.f / lrow[1];
    const int r0 = q0 + w * 16 + g;
    float* o0p = O + (size_t)(b * SEQ + r0) * DMODEL + h * HDIM;
    float* o1p = O + (size_t)(b * SEQ + r0 + 8) * DMODEL + h * HDIM;
#pragma unroll
    for (int nt = 0; nt < 8; nt++) {
        const int c = nt * 8 + tg * 2;
        float2 v0, v1;
        v0.x = cO[nt][0] * inv0; v0.y = cO[nt][1] * inv0;
        v1.x = cO[nt][2] * inv1; v1.y = cO[nt][3] * inv1;
        *(float2*)(o0p + c) = v0;
        *(float2*)(o1p + c) = v1;
    }
}

// ----------------------------------------------------------------------------
// LayerNorm (unchanged)
// ----------------------------------------------------------------------------
__global__ __launch_bounds__(256) void ln_kernel(
    const float* __restrict__ X, const float* __restrict__ g,
    const float* __restrict__ bb, float* __restrict__ Y)
{
    __shared__ float red[16];
    const int row = blockIdx.x;
    const int tid = threadIdx.x;
    const float4 xv = *(const float4*)(X + (size_t)row * DMODEL + tid * 4);

    float s  = xv.x + xv.y + xv.z + xv.w;
    float sq = xv.x*xv.x + xv.y*xv.y + xv.z*xv.z + xv.w*xv.w;
#pragma unroll
    for (int off = 16; off > 0; off >>= 1) {
        s  += __shfl_xor_sync(0xffffffffu, s,  off);
        sq += __shfl_xor_sync(0xffffffffu, sq, off);
    }
    const int warp = tid >> 5, lane = tid & 31;
    if (lane == 0) { red[warp] = s; red[warp + 8] = sq; }
    __syncthreads();
    if (warp == 0) {
        float a = (lane < 8) ? red[lane] : 0.f;
        float c = (lane < 8) ? red[lane + 8] : 0.f;
#pragma unroll
        for (int off = 4; off > 0; off >>= 1) {
            a += __shfl_xor_sync(0xffffffffu, a, off);
            c += __shfl_xor_sync(0xffffffffu, c, off);
        }
        if (lane == 0) { red[0] = a; red[1] = c; }
    }
    __syncthreads();
    const float mu  = red[0] * (1.f / DMODEL);
    const float var = red[1] * (1.f / DMODEL) - mu * mu;
    const float rstd = rsqrtf(var + LN_EPS);

    const float4 gv = *(const float4*)(g  + tid * 4);
    const float4 bv = *(const float4*)(bb + tid * 4);
    float4 yv;
    yv.x = (xv.x - mu) * rstd * gv.x + bv.x;
    yv.y = (xv.y - mu) * rstd * gv.y + bv.y;
    yv.z = (xv.z - mu) * rstd * gv.z + bv.z;
    yv.w = (xv.w - mu) * rstd * gv.w + bv.w;
    *(float4*)(Y + (size_t)row * DMODEL + tid * 4) = yv;
}

// ----------------------------------------------------------------------------
// Launch
// ----------------------------------------------------------------------------
extern "C" void kernel_launch(void* const* d_in, const int* in_sizes, int n_in,
                              void* d_out, int out_size)
{
    const float* x    = (const float*)d_in[0];
    const float* enc  = (const float*)d_in[1];
    const float* s_wq = (const float*)d_in[2];  const float* s_bq = (const float*)d_in[3];
    const float* s_wk = (const float*)d_in[4];  const float* s_bk = (const float*)d_in[5];
    const float* s_wv = (const float*)d_in[6];  const float* s_bv = (const float*)d_in[7];
    const float* s_wo = (const float*)d_in[8];  const float* s_bo = (const float*)d_in[9];
    const float* c_wq = (const float*)d_in[10]; const float* c_bq = (const float*)d_in[11];
    const float* c_wk = (const float*)d_in[12]; const float* c_bk = (const float*)d_in[13];
    const float* c_wv = (const float*)d_in[14]; const float* c_bv = (const float*)d_in[15];
    const float* c_wo = (const float*)d_in[16]; const float* c_bo = (const float*)d_in[17];
    const float* f_w1 = (const float*)d_in[18]; const float* f_b1 = (const float*)d_in[19];
    const float* f_w2 = (const float*)d_in[20]; const float* f_b2 = (const float*)d_in[21];
    const float* ln1g = (const float*)d_in[22]; const float* ln1b = (const float*)d_in[23];
    const float* ln2g = (const float*)d_in[24]; const float* ln2b = (const float*)d_in[25];
    const float* ln3g = (const float*)d_in[26]; const float* ln3b = (const float*)d_in[27];
    float* out = (float*)d_out;

    uint16_t *q, *k, *v;
    float *attn, *tmp, *y1, *y2, *ffn;
    cudaGetSymbolAddress((void**)&q,    h_q);
    cudaGetSymbolAddress((void**)&k,    h_k);
    cudaGetSymbolAddress((void**)&v,    h_v);
    cudaGetSymbolAddress((void**)&attn, g_attn);
    cudaGetSymbolAddress((void**)&tmp,  g_tmp);
    cudaGetSymbolAddress((void**)&y1,   g_y1);
    cudaGetSymbolAddress((void**)&y2,   g_y2);
    cudaGetSymbolAddress((void**)&ffn,  g_ffn);

    const dim3 blk(256);
    const dim3 ablk(256);
    const dim3 gatt(SEQ / 128, NHEADS, BATCH);
    const dim3 gln(TOK);

    GemmArgs ga;
    GemmH16Args gh;

    // ---- self attention: fused QKV projection -> fp16 (z=3) ----
    gh = GemmH16Args{};
    gh.A[0] = x;    gh.A[1] = x;    gh.A[2] = x;
    gh.W[0] = s_wq; gh.W[1] = s_wk; gh.W[2] = s_wv;
    gh.bias[0] = s_bq; gh.bias[1] = s_bk; gh.bias[2] = s_bv;
    gh.C[0] = q; gh.C[1] = k; gh.C[2] = v;
    gh.scale[0] = QSCALE; gh.scale[1] = 1.f; gh.scale[2] = 1.f;
    gh.N = DMODEL; gh.K = DMODEL;
    gemm_h16<<<dim3(DMODEL/128, TOK/128, 3), blk>>>(gh);

    attn_fp16<true><<<gatt, ablk>>>(q, k, v, attn);

    ga = GemmArgs{};
    ga.A[0] = attn; ga.W[0] = s_wo; ga.bias[0] = s_bo; ga.R[0] = x; ga.C[0] = tmp;
    ga.N = DMODEL; ga.K = DMODEL;
    gemm_bf16<false,true><<<dim3(DMODEL/128, TOK/128, 1), blk>>>(ga);
    ln_kernel<<<gln, blk>>>(tmp, ln1g, ln1b, y1);

    // ---- cross attention: fused Q(y1) + K,V(enc) projection -> fp16 ----
    gh.A[0] = y1;   gh.A[1] = enc;  gh.A[2] = enc;
    gh.W[0] = c_wq; gh.W[1] = c_wk; gh.W[2] = c_wv;
    gh.bias[0] = c_bq; gh.bias[1] = c_bk; gh.bias[2] = c_bv;
    gh.C[0] = q; gh.C[1] = k; gh.C[2] = v;
    gemm_h16<<<dim3(DMODEL/128, TOK/128, 3), blk>>>(gh);

    attn_fp16<false><<<gatt, ablk>>>(q, k, v, attn);

    ga.A[0] = attn; ga.W[0] = c_wo; ga.bias[0] = c_bo; ga.R[0] = y1; ga.C[0] = tmp;
    gemm_bf16<false,true><<<dim3(DMODEL/128, TOK/128, 1), blk>>>(ga);
    ln_kernel<<<gln, blk>>>(tmp, ln2g, ln2b, y2);

    // ---- FFN ----
    ga.A[0] = y2; ga.W[0] = f_w1; ga.bias[0] = f_b1; ga.R[0] = x; ga.C[0] = ffn;
    ga.N = DFF; ga.K = DMODEL;
    gemm_bf16<true,false><<<dim3(DFF/128, TOK/128, 1), blk>>>(ga);

    ga.A[0] = ffn; ga.W[0] = f_w2; ga.bias[0] = f_b2; ga.R[0] = y2; ga.C[0] = tmp;
    ga.N = DMODEL; ga.K = DFF;
    gemm_bf16<false,true><<<dim3(DMODEL/128, TOK/128, 1), blk>>>(ga);
    ln_kernel<<<gln, blk>>>(tmp, ln3g, ln3b, out);
}

// round 15
// speedup vs baseline: 1.0156x; 1.0156x over previous
#include <cuda_runtime.h>
#include <cuda_bf16.h>
#include <math.h>
#include <stdint.h>

// ----------------------------------------------------------------------------
// Problem constants
// ----------------------------------------------------------------------------
#define BATCH   2
#define SEQ     2048
#define TOK     (BATCH * SEQ)        // 4096 rows
#define DMODEL  1024
#define DFF     4096
#define NHEADS  16
#define HDIM    64
#define LN_EPS  1e-5f
#define QSCALE  (0.125f * 1.44269504f)

// ----------------------------------------------------------------------------
// Scratch buffers
// ----------------------------------------------------------------------------
__device__ uint16_t h_q [TOK * DMODEL];   // fp16 Q (pre-scaled by QSCALE)
__device__ uint16_t h_k [TOK * DMODEL];   // fp16 K
__device__ uint16_t h_v [TOK * DMODEL];   // fp16 V
__device__ float g_attn[TOK * DMODEL];
__device__ float g_tmp [TOK * DMODEL];
__device__ float g_y1  [TOK * DMODEL];
__device__ float g_y2  [TOK * DMODEL];
__device__ float g_ffn [TOK * DFF];

// pack two fp32 -> bf16x2 / f16x2 (first asm src -> HIGH half)
__device__ __forceinline__ uint32_t packbf(float lo, float hi) {
    uint32_t d;
    asm("cvt.rn.bf16x2.f32 %0, %1, %2;" : "=r"(d) : "f"(hi), "f"(lo));
    return d;
}
__device__ __forceinline__ uint32_t packh(float lo, float hi) {
    uint32_t d;
    asm("cvt.rn.f16x2.f32 %0, %1, %2;" : "=r"(d) : "f"(hi), "f"(lo));
    return d;
}
__device__ __forceinline__ uint32_t ex2h2(uint32_t x) {
    uint32_t r;
    asm("ex2.approx.f16x2 %0, %1;" : "=r"(r) : "r"(x));
    return r;
}
__device__ __forceinline__ uint32_t smem_u32(const void* p) {
    return (uint32_t)__cvta_generic_to_shared(p);
}

#define MMA_BF16(acc, a, b0v, b1v)                                         \
    asm volatile(                                                          \
        "mma.sync.aligned.m16n8k16.row.col.f32.bf16.bf16.f32 "             \
        "{%0,%1,%2,%3}, {%4,%5,%6,%7}, {%8,%9}, {%0,%1,%2,%3};"            \
        : "+f"((acc)[0]), "+f"((acc)[1]), "+f"((acc)[2]), "+f"((acc)[3])   \
        : "r"((a)[0]), "r"((a)[1]), "r"((a)[2]), "r"((a)[3]),              \
          "r"(b0v), "r"(b1v))

#define MMA_F16(acc, a, b0v, b1v)                                          \
    asm volatile(                                                          \
        "mma.sync.aligned.m16n8k16.row.col.f32.f16.f16.f32 "               \
        "{%0,%1,%2,%3}, {%4,%5,%6,%7}, {%8,%9}, {%0,%1,%2,%3};"            \
        : "+f"((acc)[0]), "+f"((acc)[1]), "+f"((acc)[2]), "+f"((acc)[3])   \
        : "r"((a)[0]), "r"((a)[1]), "r"((a)[2]), "r"((a)[3]),              \
          "r"(b0v), "r"(b1v))

#define LDSM_X4(r0, r1, r2, r3, addr)                                      \
    asm volatile(                                                          \
        "ldmatrix.sync.aligned.m8n8.x4.shared.b16 "                        \
        "{%0,%1,%2,%3}, [%4];"                                             \
        : "=r"(r0), "=r"(r1), "=r"(r2), "=r"(r3) : "r"(addr))

#define LDSM_X4_TRANS(r0, r1, r2, r3, addr)                                \
    asm volatile(                                                          \
        "ldmatrix.sync.aligned.m8n8.x4.trans.shared.b16 "                  \
        "{%0,%1,%2,%3}, [%4];"                                             \
        : "=r"(r0), "=r"(r1), "=r"(r2), "=r"(r3) : "r"(addr))

// ----------------------------------------------------------------------------
// Shared GEMM mainloop bits (R8-validated layout)
// ----------------------------------------------------------------------------
#define A_WSTR 12
#define B_WSTR 136
#define A_WRDS (128 * A_WSTR)
#define B_WRDS (8 * B_WSTR)

// ----------------------------------------------------------------------------
// bf16 GEMM with fp32 output (+bias, +residual, ReLU) — unchanged from R8.
// ----------------------------------------------------------------------------
struct GemmArgs {
    const float* A[3];
    const float* W[3];
    const float* bias[3];
    const float* R[3];
    float*       C[3];
    int N, K;
};

template<bool RELU, bool RES>
__global__ __launch_bounds__(256, 2) void gemm_bf16(GemmArgs args)
{
    __shared__ uint32_t As[2][A_WRDS];
    __shared__ uint32_t Bs[2][B_WRDS];

    const int zi = blockIdx.z;
    const float* __restrict__ A    = args.A[zi];
    const float* __restrict__ W    = args.W[zi];
    const float* __restrict__ bias = args.bias[zi];
    const float* __restrict__ Rp   = args.R[zi];
    float*       __restrict__ C    = args.C[zi];
    const int N = args.N, K = args.K;

    const int tid  = threadIdx.x;
    const int lane = tid & 31;
    const int warp = tid >> 5;
    const int g    = lane >> 2;
    const int tg   = lane & 3;
    const int wm   = (warp >> 2) * 64;
    const int wn   = (warp & 3) * 32;
    const int bm   = blockIdx.y * 128;
    const int bn   = blockIdx.x * 128;

    const int a_row = tid >> 2;
    const int a_c4  = (tid & 3) * 4;
    const int b_p   = tid >> 5;
    const int b_c4  = (tid & 31) * 4;

    const float* Ag0 = A + (size_t)(bm + a_row)      * K + a_c4;
    const float* Ag1 = A + (size_t)(bm + a_row + 64) * K + a_c4;
    const float* Wg0 = W + (size_t)(2 * b_p)     * N + bn + b_c4;
    const float* Wg1 = W + (size_t)(2 * b_p + 1) * N + bn + b_c4;

    float acc[4][4][4];
#pragma unroll
    for (int i = 0; i < 4; i++)
#pragma unroll
        for (int j = 0; j < 4; j++)
#pragma unroll
            for (int r = 0; r < 4; r++) acc[i][j][r] = 0.f;

    float4 ra0, ra1, rb0, rb1;

#define LOADG(t) do {                                                \
        const size_t ka = (size_t)(t) * 16;                          \
        const size_t kb = (size_t)(t) * 16 * (size_t)N;              \
        ra0 = *(const float4*)(Ag0 + ka);                            \
        ra1 = *(const float4*)(Ag1 + ka);                            \
        rb0 = *(const float4*)(Wg0 + kb);                            \
        rb1 = *(const float4*)(Wg1 + kb);                            \
    } while (0)

#define STORES(buf) do {                                             \
        uint32_t* as_ = As[buf];                                     \
        uint32_t* bs_ = Bs[buf];                                     \
        uint2 aw0, aw1;                                              \
        aw0.x = packbf(ra0.x, ra0.y); aw0.y = packbf(ra0.z, ra0.w);  \
        aw1.x = packbf(ra1.x, ra1.y); aw1.y = packbf(ra1.z, ra1.w);  \
        *(uint2*)(as_ + a_row * A_WSTR + (a_c4 >> 1)) = aw0;         \
        *(uint2*)(as_ + (a_row + 64) * A_WSTR + (a_c4 >> 1)) = aw1;  \
        uint4 bw;                                                    \
        bw.x = packbf(rb0.x, rb1.x); bw.y = packbf(rb0.y, rb1.y);    \
        bw.z = packbf(rb0.z, rb1.z); bw.w = packbf(rb0.w, rb1.w);    \
        *(uint4*)(bs_ + b_p * B_WSTR + b_c4) = bw;                   \
    } while (0)

    const int NT = K >> 4;

    LOADG(0);
    STORES(0);
    __syncthreads();

    for (int t = 0; t < NT; t++) {
        const int cur = t & 1;
        if (t + 1 < NT) LOADG(t + 1);

        const uint32_t* as_ = As[cur];
        const uint32_t* bs_ = Bs[cur];

        unsigned af[4][4], bf2[4][2];
#pragma unroll
        for (int mt = 0; mt < 4; mt++) {
            const uint32_t* ap = as_ + (wm + mt * 16 + g) * A_WSTR + tg;
            af[mt][0] = ap[0];
            af[mt][1] = ap[8 * A_WSTR];
            af[mt][2] = ap[4];
            af[mt][3] = ap[8 * A_WSTR + 4];
        }
#pragma unroll
        for (int nt = 0; nt < 4; nt++) {
            const int col = wn + nt * 8 + g;
            bf2[nt][0] = bs_[tg * B_WSTR + col];
            bf2[nt][1] = bs_[(tg + 4) * B_WSTR + col];
        }
#pragma unroll
        for (int mt = 0; mt < 4; mt++)
#pragma unroll
            for (int nt = 0; nt < 4; nt++)
                MMA_BF16(acc[mt][nt], af[mt], bf2[nt][0], bf2[nt][1]);

        if (t + 1 < NT) STORES((t + 1) & 1);
        __syncthreads();
    }

#pragma unroll
    for (int mt = 0; mt < 4; mt++) {
        const int row0 = bm + wm + mt * 16 + g;
#pragma unroll
        for (int nt = 0; nt < 4; nt++) {
            const int col = bn + wn + nt * 8 + tg * 2;
            const float bv0 = bias[col], bv1 = bias[col + 1];
            float2 v0, v1;
            v0.x = acc[mt][nt][0] + bv0; v0.y = acc[mt][nt][1] + bv1;
            v1.x = acc[mt][nt][2] + bv0; v1.y = acc[mt][nt][3] + bv1;
            if (RES) {
                float2 r0 = *(const float2*)(Rp + (size_t)row0 * N + col);
                float2 r1 = *(const float2*)(Rp + (size_t)(row0 + 8) * N + col);
                v0.x += r0.x; v0.y += r0.y;
                v1.x += r1.x; v1.y += r1.y;
            }
            if (RELU) {
                v0.x = fmaxf(v0.x, 0.f); v0.y = fmaxf(v0.y, 0.f);
                v1.x = fmaxf(v1.x, 0.f); v1.y = fmaxf(v1.y, 0.f);
            }
            *(float2*)(C + (size_t)row0 * N + col)       = v0;
            *(float2*)(C + (size_t)(row0 + 8) * N + col) = v1;
        }
    }
#undef LOADG
#undef STORES
}

// ----------------------------------------------------------------------------
// bf16 GEMM with fp16 output: C16 = f16((A@W + bias) * scale).
// ----------------------------------------------------------------------------
struct GemmH16Args {
    const float* A[3];
    const float* W[3];
    const float* bias[3];
    uint16_t*    C[3];
    float        scale[3];
    int N, K;
};

__global__ __launch_bounds__(256, 2) void gemm_h16(GemmH16Args args)
{
    __shared__ uint32_t As[2][A_WRDS];
    __shared__ uint32_t Bs[2][B_WRDS];

    const int zi = blockIdx.z;
    const float* __restrict__ A    = args.A[zi];
    const float* __restrict__ W    = args.W[zi];
    const float* __restrict__ bias = args.bias[zi];
    uint16_t*    __restrict__ C16  = args.C[zi];
    const float sc = args.scale[zi];
    const int N = args.N, K = args.K;

    const int tid  = threadIdx.x;
    const int lane = tid & 31;
    const int warp = tid >> 5;
    const int g    = lane >> 2;
    const int tg   = lane & 3;
    const int wm   = (warp >> 2) * 64;
    const int wn   = (warp & 3) * 32;
    const int bm   = blockIdx.y * 128;
    const int bn   = blockIdx.x * 128;

    const int a_row = tid >> 2;
    const int a_c4  = (tid & 3) * 4;
    const int b_p   = tid >> 5;
    const int b_c4  = (tid & 31) * 4;

    const float* Ag0 = A + (size_t)(bm + a_row)      * K + a_c4;
    const float* Ag1 = A + (size_t)(bm + a_row + 64) * K + a_c4;
    const float* Wg0 = W + (size_t)(2 * b_p)     * N + bn + b_c4;
    const float* Wg1 = W + (size_t)(2 * b_p + 1) * N + bn + b_c4;

    float acc[4][4][4];
#pragma unroll
    for (int i = 0; i < 4; i++)
#pragma unroll
        for (int j = 0; j < 4; j++)
#pragma unroll
            for (int r = 0; r < 4; r++) acc[i][j][r] = 0.f;

    float4 ra0, ra1, rb0, rb1;

#define LOADG(t) do {                                                \
        const size_t ka = (size_t)(t) * 16;                          \
        const size_t kb = (size_t)(t) * 16 * (size_t)N;              \
        ra0 = *(const float4*)(Ag0 + ka);                            \
        ra1 = *(const float4*)(Ag1 + ka);                            \
        rb0 = *(const float4*)(Wg0 + kb);                            \
        rb1 = *(const float4*)(Wg1 + kb);                            \
    } while (0)

#define STORES(buf) do {                                             \
        uint32_t* as_ = As[buf];                                     \
        uint32_t* bs_ = Bs[buf];                                     \
        uint2 aw0, aw1;                                              \
        aw0.x = packbf(ra0.x, ra0.y); aw0.y = packbf(ra0.z, ra0.w);  \
        aw1.x = packbf(ra1.x, ra1.y); aw1.y = packbf(ra1.z, ra1.w);  \
        *(uint2*)(as_ + a_row * A_WSTR + (a_c4 >> 1)) = aw0;         \
        *(uint2*)(as_ + (a_row + 64) * A_WSTR + (a_c4 >> 1)) = aw1;  \
        uint4 bw;                                                    \
        bw.x = packbf(rb0.x, rb1.x); bw.y = packbf(rb0.y, rb1.y);    \
        bw.z = packbf(rb0.z, rb1.z); bw.w = packbf(rb0.w, rb1.w);    \
        *(uint4*)(bs_ + b_p * B_WSTR + b_c4) = bw;                   \
    } while (0)

    const int NT = K >> 4;

    LOADG(0);
    STORES(0);
    __syncthreads();

    for (int t = 0; t < NT; t++) {
        const int cur = t & 1;
        if (t + 1 < NT) LOADG(t + 1);

        const uint32_t* as_ = As[cur];
        const uint32_t* bs_ = Bs[cur];

        unsigned af[4][4], bf2[4][2];
#pragma unroll
        for (int mt = 0; mt < 4; mt++) {
            const uint32_t* ap = as_ + (wm + mt * 16 + g) * A_WSTR + tg;
            af[mt][0] = ap[0];
            af[mt][1] = ap[8 * A_WSTR];
            af[mt][2] = ap[4];
            af[mt][3] = ap[8 * A_WSTR + 4];
        }
#pragma unroll
        for (int nt = 0; nt < 4; nt++) {
            const int col = wn + nt * 8 + g;
            bf2[nt][0] = bs_[tg * B_WSTR + col];
            bf2[nt][1] = bs_[(tg + 4) * B_WSTR + col];
        }
#pragma unroll
        for (int mt = 0; mt < 4; mt++)
#pragma unroll
            for (int nt = 0; nt < 4; nt++)
                MMA_BF16(acc[mt][nt], af[mt], bf2[nt][0], bf2[nt][1]);

        if (t + 1 < NT) STORES((t + 1) & 1);
        __syncthreads();
    }

#pragma unroll
    for (int mt = 0; mt < 4; mt++) {
        const int row0 = bm + wm + mt * 16 + g;
#pragma unroll
        for (int nt = 0; nt < 4; nt++) {
            const int col = bn + wn + nt * 8 + tg * 2;
            const float bv0 = bias[col], bv1 = bias[col + 1];
            const uint32_t w0 = packh((acc[mt][nt][0] + bv0) * sc,
                                      (acc[mt][nt][1] + bv1) * sc);
            const uint32_t w1 = packh((acc[mt][nt][2] + bv0) * sc,
                                      (acc[mt][nt][3] + bv1) * sc);
            *(uint32_t*)(C16 + (size_t)row0 * N + col)       = w0;
            *(uint32_t*)(C16 + (size_t)(row0 + 8) * N + col) = w1;
        }
    }
#undef LOADG
#undef STORES
}

// ----------------------------------------------------------------------------
// fp16 flash attention (R13 shape: 64-row q-tile, 128 threads), K B-frags
// now loaded via ldmatrix.x4 (16 instructions/tile instead of 64 LDS).
// ----------------------------------------------------------------------------
#define HSTR 72            // halves per smem row (64 + 8 pad)

template<bool CAUSAL>
__global__ __launch_bounds__(128) void attn_fp16(
    const uint16_t* __restrict__ Q, const uint16_t* __restrict__ K,
    const uint16_t* __restrict__ V, float* __restrict__ O)
{
    __shared__ __align__(16) uint16_t sQ[64 * HSTR];
    __shared__ __align__(16) uint16_t sK[64 * HSTR];
    __shared__ __align__(16) uint16_t sV[64 * HSTR];
    uint32_t* sQw = (uint32_t*)sQ;     // word stride 36
    uint32_t* sKw = (uint32_t*)sK;

    const int b  = blockIdx.z;
    const int h  = blockIdx.y;
    const int q0 = blockIdx.x * 64;
    const int tid  = threadIdx.x;
    const int lane = tid & 31;
    const int w    = tid >> 5;
    const int g    = lane >> 2;
    const int tg   = lane & 3;
    const size_t hoff = ((size_t)(b * NHEADS + h)) * SEQ * HDIM;
    const uint32_t sKbase = smem_u32(sK);
    const uint32_t sVbase = smem_u32(sV);

    // ---- stage Q: 64 rows x 8 uint4 = 512 copies, 4/thread ----
#pragma unroll
    for (int i = 0; i < 4; i++) {
        const int idx = tid + i * 128;
        const int row = idx >> 3;
        const int c8  = idx & 7;
        uint4 qv = *(const uint4*)(Q + hoff + (size_t)(q0 + row) * HDIM + c8 * 8);
        *(uint4*)(sQw + row * 36 + c8 * 4) = qv;
    }
    __syncthreads();

    // ---- Q fragments (register resident); rows = w*16 + {g, g+8} ----
    uint32_t aQ[4][4];
#pragma unroll
    for (int kk = 0; kk < 4; kk++) {
        const uint32_t* qb = sQw + (w * 16 + g) * 36 + kk * 8 + tg;
        aQ[kk][0] = qb[0];
        aQ[kk][1] = qb[8 * 36];
        aQ[kk][2] = qb[4];
        aQ[kk][3] = qb[8 * 36 + 4];
    }

    float cO[8][4];
#pragma unroll
    for (int nt = 0; nt < 8; nt++)
#pragma unroll
        for (int r = 0; r < 4; r++) cO[nt][r] = 0.f;
    float lrow[2] = { 0.f, 0.f };

    const int ntiles = CAUSAL ? (q0 / 64 + 1) : (SEQ / 64);

    // ldmatrix lane decomposition (shared by K and V fragment loads)
    const int mat = lane >> 3;      // 0..3
    const int mr  = lane & 7;       // 0..7

    for (int t = 0; t < ntiles; t++) {
        const int j0 = t * 64;
        __syncthreads();
        // ---- stage K, V: uint4 copies ----
#pragma unroll
        for (int i = 0; i < 4; i++) {
            const int idx = tid + i * 128;
            const int row = idx >> 3;
            const int c8  = idx & 7;
            const size_t gaddr = hoff + (size_t)(j0 + row) * HDIM + c8 * 8;
            uint4 kv = *(const uint4*)(K + gaddr);
            *(uint4*)(sKw + row * 36 + c8 * 4) = kv;
            uint4 vv = *(const uint4*)(V + gaddr);
            *(uint4*)((uint32_t*)sV + row * 36 + c8 * 4) = vv;
        }
        __syncthreads();

        // ---- S = Q @ K^T : K B-frags via ldmatrix.x4 (non-trans) ----
        float cS[8][4];
#pragma unroll
        for (int nt = 0; nt < 8; nt++)
#pragma unroll
            for (int r = 0; r < 4; r++) cS[nt][r] = 0.f;

#pragma unroll
        for (int kk = 0; kk < 4; kk++)
#pragma unroll
            for (int ntp = 0; ntp < 4; ntp++) {
                // matrix m: K rows (2*ntp + (m>>1))*8 + mr, d cols kk*16 + (m&1)*8
                const int key = (ntp * 2 + (mat >> 1)) * 8 + mr;
                const int dcl = kk * 16 + (mat & 1) * 8;
                const uint32_t addr = sKbase + (uint32_t)(key * HSTR + dcl) * 2;
                uint32_t b0, b1, b2, b3;
                LDSM_X4(b0, b1, b2, b3, addr);
                MMA_F16(cS[2 * ntp],     aQ[kk], b0, b1);
                MMA_F16(cS[2 * ntp + 1], aQ[kk], b2, b3);
            }

        // ---- causal mask (diagonal tile only) ----
        if (CAUSAL && t == ntiles - 1) {
            const int rbase = q0 + w * 16 + g;
#pragma unroll
            for (int nt = 0; nt < 8; nt++) {
                const int c0 = j0 + nt * 8 + tg * 2;
                if (c0     > rbase)     cS[nt][0] = -1e30f;
                if (c0 + 1 > rbase)     cS[nt][1] = -1e30f;
                if (c0     > rbase + 8) cS[nt][2] = -1e30f;
                if (c0 + 1 > rbase + 8) cS[nt][3] = -1e30f;
            }
        }

        // ---- p = 2^S, packed f16x2 (these ARE the PV A-frag words) ----
        uint32_t plo[8], phi[8];
#pragma unroll
        for (int nt = 0; nt < 8; nt++) {
            plo[nt] = ex2h2(packh(cS[nt][0], cS[nt][1]));
            phi[nt] = ex2h2(packh(cS[nt][2], cS[nt][3]));
        }

        uint32_t aP[4][4];
#pragma unroll
        for (int kk = 0; kk < 4; kk++) {
            aP[kk][0] = plo[2 * kk];
            aP[kk][1] = phi[2 * kk];
            aP[kk][2] = plo[2 * kk + 1];
            aP[kk][3] = phi[2 * kk + 1];
        }

        // ---- row sums via mma with B = ones (fp32 accumulate) ----
        {
            float cSum[4] = { 0.f, 0.f, 0.f, 0.f };
#pragma unroll
            for (int kk = 0; kk < 4; kk++)
                MMA_F16(cSum, aP[kk], 0x3C003C00u, 0x3C003C00u);
            lrow[0] += cSum[0];
            lrow[1] += cSum[2];
        }

        // ---- O += P @ V : V B-frags via ldmatrix.x4.trans ----
#pragma unroll
        for (int kk = 0; kk < 4; kk++)
#pragma unroll
            for (int np = 0; np < 4; np++) {
                const int key = kk * 16 + (mat & 1) * 8 + mr;
                const int dcl = np * 16 + (mat >> 1) * 8;
                const uint32_t addr = sVbase + (uint32_t)(key * HSTR + dcl) * 2;
                uint32_t v0, v1, v2, v3;
                LDSM_X4_TRANS(v0, v1, v2, v3, addr);
                MMA_F16(cO[2 * np],     aP[kk], v0, v1);
                MMA_F16(cO[2 * np + 1], aP[kk], v2, v3);
            }
    }

    // ---- epilogue: normalize and store (folds head transpose) ----
    const float inv0 = 1.f / lrow[0];
    const float inv1 = 1.f / lrow[1];
    const int r0 = q0 + w * 16 + g;
    float* o0p = O + (size_t)(b * SEQ + r0) * DMODEL + h * HDIM;
    float* o1p = O + (size_t)(b * SEQ + r0 + 8) * DMODEL + h * HDIM;
#pragma unroll
    for (int nt = 0; nt < 8; nt++) {
        const int c = nt * 8 + tg * 2;
        float2 v0, v1;
        v0.x = cO[nt][0] * inv0; v0.y = cO[nt][1] * inv0;
        v1.x = cO[nt][2] * inv1; v1.y = cO[nt][3] * inv1;
        *(float2*)(o0p + c) = v0;
        *(float2*)(o1p + c) = v1;
    }
}

// ----------------------------------------------------------------------------
// LayerNorm (unchanged)
// ----------------------------------------------------------------------------
__global__ __launch_bounds__(256) void ln_kernel(
    const float* __restrict__ X, const float* __restrict__ g,
    const float* __restrict__ bb, float* __restrict__ Y)
{
    __shared__ float red[16];
    const int row = blockIdx.x;
    const int tid = threadIdx.x;
    const float4 xv = *(const float4*)(X + (size_t)row * DMODEL + tid * 4);

    float s  = xv.x + xv.y + xv.z + xv.w;
    float sq = xv.x*xv.x + xv.y*xv.y + xv.z*xv.z + xv.w*xv.w;
#pragma unroll
    for (int off = 16; off > 0; off >>= 1) {
        s  += __shfl_xor_sync(0xffffffffu, s,  off);
        sq += __shfl_xor_sync(0xffffffffu, sq, off);
    }
    const int warp = tid >> 5, lane = tid & 31;
    if (lane == 0) { red[warp] = s; red[warp + 8] = sq; }
    __syncthreads();
    if (warp == 0) {
        float a = (lane < 8) ? red[lane] : 0.f;
        float c = (lane < 8) ? red[lane + 8] : 0.f;
#pragma unroll
        for (int off = 4; off > 0; off >>= 1) {
            a += __shfl_xor_sync(0xffffffffu, a, off);
            c += __shfl_xor_sync(0xffffffffu, c, off);
        }
        if (lane == 0) { red[0] = a; red[1] = c; }
    }
    __syncthreads();
    const float mu  = red[0] * (1.f / DMODEL);
    const float var = red[1] * (1.f / DMODEL) - mu * mu;
    const float rstd = rsqrtf(var + LN_EPS);

    const float4 gv = *(const float4*)(g  + tid * 4);
    const float4 bv = *(const float4*)(bb + tid * 4);
    float4 yv;
    yv.x = (xv.x - mu) * rstd * gv.x + bv.x;
    yv.y = (xv.y - mu) * rstd * gv.y + bv.y;
    yv.z = (xv.z - mu) * rstd * gv.z + bv.z;
    yv.w = (xv.w - mu) * rstd * gv.w + bv.w;
    *(float4*)(Y + (size_t)row * DMODEL + tid * 4) = yv;
}

// ----------------------------------------------------------------------------
// Launch
// ----------------------------------------------------------------------------
extern "C" void kernel_launch(void* const* d_in, const int* in_sizes, int n_in,
                              void* d_out, int out_size)
{
    const float* x    = (const float*)d_in[0];
    const float* enc  = (const float*)d_in[1];
    const float* s_wq = (const float*)d_in[2];  const float* s_bq = (const float*)d_in[3];
    const float* s_wk = (const float*)d_in[4];  const float* s_bk = (const float*)d_in[5];
    const float* s_wv = (const float*)d_in[6];  const float* s_bv = (const float*)d_in[7];
    const float* s_wo = (const float*)d_in[8];  const float* s_bo = (const float*)d_in[9];
    const float* c_wq = (const float*)d_in[10]; const float* c_bq = (const float*)d_in[11];
    const float* c_wk = (const float*)d_in[12]; const float* c_bk = (const float*)d_in[13];
    const float* c_wv = (const float*)d_in[14]; const float* c_bv = (const float*)d_in[15];
    const float* c_wo = (const float*)d_in[16]; const float* c_bo = (const float*)d_in[17];
    const float* f_w1 = (const float*)d_in[18]; const float* f_b1 = (const float*)d_in[19];
    const float* f_w2 = (const float*)d_in[20]; const float* f_b2 = (const float*)d_in[21];
    const float* ln1g = (const float*)d_in[22]; const float* ln1b = (const float*)d_in[23];
    const float* ln2g = (const float*)d_in[24]; const float* ln2b = (const float*)d_in[25];
    const float* ln3g = (const float*)d_in[26]; const float* ln3b = (const float*)d_in[27];
    float* out = (float*)d_out;

    uint16_t *q, *k, *v;
    float *attn, *tmp, *y1, *y2, *ffn;
    cudaGetSymbolAddress((void**)&q,    h_q);
    cudaGetSymbolAddress((void**)&k,    h_k);
    cudaGetSymbolAddress((void**)&v,    h_v);
    cudaGetSymbolAddress((void**)&attn, g_attn);
    cudaGetSymbolAddress((void**)&tmp,  g_tmp);
    cudaGetSymbolAddress((void**)&y1,   g_y1);
    cudaGetSymbolAddress((void**)&y2,   g_y2);
    cudaGetSymbolAddress((void**)&ffn,  g_ffn);

    const dim3 blk(256);
    const dim3 ablk(128);
    const dim3 gatt(SEQ / 64, NHEADS, BATCH);
    const dim3 gln(TOK);

    GemmArgs ga;
    GemmH16Args gh;

    // ---- self attention: fused QKV projection -> fp16 (z=3) ----
    gh = GemmH16Args{};
    gh.A[0] = x;    gh.A[1] = x;    gh.A[2] = x;
    gh.W[0] = s_wq; gh.W[1] = s_wk; gh.W[2] = s_wv;
    gh.bias[0] = s_bq; gh.bias[1] = s_bk; gh.bias[2] = s_bv;
    gh.C[0] = q; gh.C[1] = k; gh.C[2] = v;
    gh.scale[0] = QSCALE; gh.scale[1] = 1.f; gh.scale[2] = 1.f;
    gh.N = DMODEL; gh.K = DMODEL;
    gemm_h16<<<dim3(DMODEL/128, TOK/128, 3), blk>>>(gh);

    attn_fp16<true><<<gatt, ablk>>>(q, k, v, attn);

    ga = GemmArgs{};
    ga.A[0] = attn; ga.W[0] = s_wo; ga.bias[0] = s_bo; ga.R[0] = x; ga.C[0] = tmp;
    ga.N = DMODEL; ga.K = DMODEL;
    gemm_bf16<false,true><<<dim3(DMODEL/128, TOK/128, 1), blk>>>(ga);
    ln_kernel<<<gln, blk>>>(tmp, ln1g, ln1b, y1);

    // ---- cross attention: fused Q(y1) + K,V(enc) projection -> fp16 ----
    gh.A[0] = y1;   gh.A[1] = enc;  gh.A[2] = enc;
    gh.W[0] = c_wq; gh.W[1] = c_wk; gh.W[2] = c_wv;
    gh.bias[0] = c_bq; gh.bias[1] = c_bk; gh.bias[2] = c_bv;
    gh.C[0] = q; gh.C[1] = k; gh.C[2] = v;
    gemm_h16<<<dim3(DMODEL/128, TOK/128, 3), blk>>>(gh);

    attn_fp16<false><<<gatt, ablk>>>(q, k, v, attn);

    ga.A[0] = attn; ga.W[0] = c_wo; ga.bias[0] = c_bo; ga.R[0] = y1; ga.C[0] = tmp;
    gemm_bf16<false,true><<<dim3(DMODEL/128, TOK/128, 1), blk>>>(ga);
    ln_kernel<<<gln, blk>>>(tmp, ln2g, ln2b, y2);

    // ---- FFN ----
    ga.A[0] = y2; ga.W[0] = f_w1; ga.bias[0] = f_b1; ga.R[0] = x; ga.C[0] = ffn;
    ga.N = DFF; ga.K = DMODEL;
    gemm_bf16<true,false><<<dim3(DFF/128, TOK/128, 1), blk>>>(ga);

    ga.A[0] = ffn; ga.W[0] = f_w2; ga.bias[0] = f_b2; ga.R[0] = y2; ga.C[0] = tmp;
    ga.N = DMODEL; ga.K = DFF;
    gemm_bf16<false,true><<<dim3(DMODEL/128, TOK/128, 1), blk>>>(ga);
    ln_kernel<<<gln, blk>>>(tmp, ln3g, ln3b, out);
}

// round 16
// speedup vs baseline: 1.0353x; 1.0194x over previous
#include <cuda_runtime.h>
#include <cuda_bf16.h>
#include <math.h>
#include <stdint.h>

// ----------------------------------------------------------------------------
// Problem constants
// ----------------------------------------------------------------------------
#define BATCH   2
#define SEQ     2048
#define TOK     (BATCH * SEQ)        // 4096 rows
#define DMODEL  1024
#define DFF     4096
#define NHEADS  16
#define HDIM    64
#define LN_EPS  1e-5f
#define QSCALE  (0.125f * 1.44269504f)

// ----------------------------------------------------------------------------
// Scratch buffers
// ----------------------------------------------------------------------------
__device__ uint16_t h_q [TOK * DMODEL];   // fp16 Q (pre-scaled by QSCALE)
__device__ uint16_t h_k [TOK * DMODEL];   // fp16 K
__device__ uint16_t h_v [TOK * DMODEL];   // fp16 V
__device__ float g_attn[TOK * DMODEL];
__device__ float g_tmp [TOK * DMODEL];
__device__ float g_y1  [TOK * DMODEL];
__device__ float g_y2  [TOK * DMODEL];
__device__ float g_ffn [TOK * DFF];

// pack two fp32 -> bf16x2 / f16x2 (first asm src -> HIGH half)
__device__ __forceinline__ uint32_t packbf(float lo, float hi) {
    uint32_t d;
    asm("cvt.rn.bf16x2.f32 %0, %1, %2;" : "=r"(d) : "f"(hi), "f"(lo));
    return d;
}
__device__ __forceinline__ uint32_t packh(float lo, float hi) {
    uint32_t d;
    asm("cvt.rn.f16x2.f32 %0, %1, %2;" : "=r"(d) : "f"(hi), "f"(lo));
    return d;
}
__device__ __forceinline__ uint32_t ex2h2(uint32_t x) {
    uint32_t r;
    asm("ex2.approx.f16x2 %0, %1;" : "=r"(r) : "r"(x));
    return r;
}
__device__ __forceinline__ uint32_t smem_u32(const void* p) {
    return (uint32_t)__cvta_generic_to_shared(p);
}
__device__ __forceinline__ void cp_async16(uint32_t smem, const void* gptr) {
    asm volatile("cp.async.cg.shared.global [%0], [%1], 16;"
                 :: "r"(smem), "l"(gptr));
}
#define CP_COMMIT() asm volatile("cp.async.commit_group;")
#define CP_WAIT(n)  asm volatile("cp.async.wait_group %0;" :: "n"(n))

#define MMA_BF16(acc, a, b0v, b1v)                                         \
    asm volatile(                                                          \
        "mma.sync.aligned.m16n8k16.row.col.f32.bf16.bf16.f32 "             \
        "{%0,%1,%2,%3}, {%4,%5,%6,%7}, {%8,%9}, {%0,%1,%2,%3};"            \
        : "+f"((acc)[0]), "+f"((acc)[1]), "+f"((acc)[2]), "+f"((acc)[3])   \
        : "r"((a)[0]), "r"((a)[1]), "r"((a)[2]), "r"((a)[3]),              \
          "r"(b0v), "r"(b1v))

#define MMA_F16(acc, a, b0v, b1v)                                          \
    asm volatile(                                                          \
        "mma.sync.aligned.m16n8k16.row.col.f32.f16.f16.f32 "               \
        "{%0,%1,%2,%3}, {%4,%5,%6,%7}, {%8,%9}, {%0,%1,%2,%3};"            \
        : "+f"((acc)[0]), "+f"((acc)[1]), "+f"((acc)[2]), "+f"((acc)[3])   \
        : "r"((a)[0]), "r"((a)[1]), "r"((a)[2]), "r"((a)[3]),              \
          "r"(b0v), "r"(b1v))

#define LDSM_X4(r0, r1, r2, r3, addr)                                      \
    asm volatile(                                                          \
        "ldmatrix.sync.aligned.m8n8.x4.shared.b16 "                        \
        "{%0,%1,%2,%3}, [%4];"                                             \
        : "=r"(r0), "=r"(r1), "=r"(r2), "=r"(r3) : "r"(addr))

#define LDSM_X4_TRANS(r0, r1, r2, r3, addr)                                \
    asm volatile(                                                          \
        "ldmatrix.sync.aligned.m8n8.x4.trans.shared.b16 "                  \
        "{%0,%1,%2,%3}, [%4];"                                             \
        : "=r"(r0), "=r"(r1), "=r"(r2), "=r"(r3) : "r"(addr))

// ----------------------------------------------------------------------------
// Shared GEMM mainloop bits (R8-validated layout)
// ----------------------------------------------------------------------------
#define A_WSTR 12
#define B_WSTR 136
#define A_WRDS (128 * A_WSTR)
#define B_WRDS (8 * B_WSTR)

// ----------------------------------------------------------------------------
// bf16 GEMM with fp32 output (+bias, +residual, ReLU) — unchanged from R8.
// ----------------------------------------------------------------------------
struct GemmArgs {
    const float* A[3];
    const float* W[3];
    const float* bias[3];
    const float* R[3];
    float*       C[3];
    int N, K;
};

template<bool RELU, bool RES>
__global__ __launch_bounds__(256, 2) void gemm_bf16(GemmArgs args)
{
    __shared__ uint32_t As[2][A_WRDS];
    __shared__ uint32_t Bs[2][B_WRDS];

    const int zi = blockIdx.z;
    const float* __restrict__ A    = args.A[zi];
    const float* __restrict__ W    = args.W[zi];
    const float* __restrict__ bias = args.bias[zi];
    const float* __restrict__ Rp   = args.R[zi];
    float*       __restrict__ C    = args.C[zi];
    const int N = args.N, K = args.K;

    const int tid  = threadIdx.x;
    const int lane = tid & 31;
    const int warp = tid >> 5;
    const int g    = lane >> 2;
    const int tg   = lane & 3;
    const int wm   = (warp >> 2) * 64;
    const int wn   = (warp & 3) * 32;
    const int bm   = blockIdx.y * 128;
    const int bn   = blockIdx.x * 128;

    const int a_row = tid >> 2;
    const int a_c4  = (tid & 3) * 4;
    const int b_p   = tid >> 5;
    const int b_c4  = (tid & 31) * 4;

    const float* Ag0 = A + (size_t)(bm + a_row)      * K + a_c4;
    const float* Ag1 = A + (size_t)(bm + a_row + 64) * K + a_c4;
    const float* Wg0 = W + (size_t)(2 * b_p)     * N + bn + b_c4;
    const float* Wg1 = W + (size_t)(2 * b_p + 1) * N + bn + b_c4;

    float acc[4][4][4];
#pragma unroll
    for (int i = 0; i < 4; i++)
#pragma unroll
        for (int j = 0; j < 4; j++)
#pragma unroll
            for (int r = 0; r < 4; r++) acc[i][j][r] = 0.f;

    float4 ra0, ra1, rb0, rb1;

#define LOADG(t) do {                                                \
        const size_t ka = (size_t)(t) * 16;                          \
        const size_t kb = (size_t)(t) * 16 * (size_t)N;              \
        ra0 = *(const float4*)(Ag0 + ka);                            \
        ra1 = *(const float4*)(Ag1 + ka);                            \
        rb0 = *(const float4*)(Wg0 + kb);                            \
        rb1 = *(const float4*)(Wg1 + kb);                            \
    } while (0)

#define STORES(buf) do {                                             \
        uint32_t* as_ = As[buf];                                     \
        uint32_t* bs_ = Bs[buf];                                     \
        uint2 aw0, aw1;                                              \
        aw0.x = packbf(ra0.x, ra0.y); aw0.y = packbf(ra0.z, ra0.w);  \
        aw1.x = packbf(ra1.x, ra1.y); aw1.y = packbf(ra1.z, ra1.w);  \
        *(uint2*)(as_ + a_row * A_WSTR + (a_c4 >> 1)) = aw0;         \
        *(uint2*)(as_ + (a_row + 64) * A_WSTR + (a_c4 >> 1)) = aw1;  \
        uint4 bw;                                                    \
        bw.x = packbf(rb0.x, rb1.x); bw.y = packbf(rb0.y, rb1.y);    \
        bw.z = packbf(rb0.z, rb1.z); bw.w = packbf(rb0.w, rb1.w);    \
        *(uint4*)(bs_ + b_p * B_WSTR + b_c4) = bw;                   \
    } while (0)

    const int NT = K >> 4;

    LOADG(0);
    STORES(0);
    __syncthreads();

    for (int t = 0; t < NT; t++) {
        const int cur = t & 1;
        if (t + 1 < NT) LOADG(t + 1);

        const uint32_t* as_ = As[cur];
        const uint32_t* bs_ = Bs[cur];

        unsigned af[4][4], bf2[4][2];
#pragma unroll
        for (int mt = 0; mt < 4; mt++) {
            const uint32_t* ap = as_ + (wm + mt * 16 + g) * A_WSTR + tg;
            af[mt][0] = ap[0];
            af[mt][1] = ap[8 * A_WSTR];
            af[mt][2] = ap[4];
            af[mt][3] = ap[8 * A_WSTR + 4];
        }
#pragma unroll
        for (int nt = 0; nt < 4; nt++) {
            const int col = wn + nt * 8 + g;
            bf2[nt][0] = bs_[tg * B_WSTR + col];
            bf2[nt][1] = bs_[(tg + 4) * B_WSTR + col];
        }
#pragma unroll
        for (int mt = 0; mt < 4; mt++)
#pragma unroll
            for (int nt = 0; nt < 4; nt++)
                MMA_BF16(acc[mt][nt], af[mt], bf2[nt][0], bf2[nt][1]);

        if (t + 1 < NT) STORES((t + 1) & 1);
        __syncthreads();
    }

#pragma unroll
    for (int mt = 0; mt < 4; mt++) {
        const int row0 = bm + wm + mt * 16 + g;
#pragma unroll
        for (int nt = 0; nt < 4; nt++) {
            const int col = bn + wn + nt * 8 + tg * 2;
            const float bv0 = bias[col], bv1 = bias[col + 1];
            float2 v0, v1;
            v0.x = acc[mt][nt][0] + bv0; v0.y = acc[mt][nt][1] + bv1;
            v1.x = acc[mt][nt][2] + bv0; v1.y = acc[mt][nt][3] + bv1;
            if (RES) {
                float2 r0 = *(const float2*)(Rp + (size_t)row0 * N + col);
                float2 r1 = *(const float2*)(Rp + (size_t)(row0 + 8) * N + col);
                v0.x += r0.x; v0.y += r0.y;
                v1.x += r1.x; v1.y += r1.y;
            }
            if (RELU) {
                v0.x = fmaxf(v0.x, 0.f); v0.y = fmaxf(v0.y, 0.f);
                v1.x = fmaxf(v1.x, 0.f); v1.y = fmaxf(v1.y, 0.f);
            }
            *(float2*)(C + (size_t)row0 * N + col)       = v0;
            *(float2*)(C + (size_t)(row0 + 8) * N + col) = v1;
        }
    }
#undef LOADG
#undef STORES
}

// ----------------------------------------------------------------------------
// bf16 GEMM with fp16 output: C16 = f16((A@W + bias) * scale).
// ----------------------------------------------------------------------------
struct GemmH16Args {
    const float* A[3];
    const float* W[3];
    const float* bias[3];
    uint16_t*    C[3];
    float        scale[3];
    int N, K;
};

__global__ __launch_bounds__(256, 2) void gemm_h16(GemmH16Args args)
{
    __shared__ uint32_t As[2][A_WRDS];
    __shared__ uint32_t Bs[2][B_WRDS];

    const int zi = blockIdx.z;
    const float* __restrict__ A    = args.A[zi];
    const float* __restrict__ W    = args.W[zi];
    const float* __restrict__ bias = args.bias[zi];
    uint16_t*    __restrict__ C16  = args.C[zi];
    const float sc = args.scale[zi];
    const int N = args.N, K = args.K;

    const int tid  = threadIdx.x;
    const int lane = tid & 31;
    const int warp = tid >> 5;
    const int g    = lane >> 2;
    const int tg   = lane & 3;
    const int wm   = (warp >> 2) * 64;
    const int wn   = (warp & 3) * 32;
    const int bm   = blockIdx.y * 128;
    const int bn   = blockIdx.x * 128;

    const int a_row = tid >> 2;
    const int a_c4  = (tid & 3) * 4;
    const int b_p   = tid >> 5;
    const int b_c4  = (tid & 31) * 4;

    const float* Ag0 = A + (size_t)(bm + a_row)      * K + a_c4;
    const float* Ag1 = A + (size_t)(bm + a_row + 64) * K + a_c4;
    const float* Wg0 = W + (size_t)(2 * b_p)     * N + bn + b_c4;
    const float* Wg1 = W + (size_t)(2 * b_p + 1) * N + bn + b_c4;

    float acc[4][4][4];
#pragma unroll
    for (int i = 0; i < 4; i++)
#pragma unroll
        for (int j = 0; j < 4; j++)
#pragma unroll
            for (int r = 0; r < 4; r++) acc[i][j][r] = 0.f;

    float4 ra0, ra1, rb0, rb1;

#define LOADG(t) do {                                                \
        const size_t ka = (size_t)(t) * 16;                          \
        const size_t kb = (size_t)(t) * 16 * (size_t)N;              \
        ra0 = *(const float4*)(Ag0 + ka);                            \
        ra1 = *(const float4*)(Ag1 + ka);                            \
        rb0 = *(const float4*)(Wg0 + kb);                            \
        rb1 = *(const float4*)(Wg1 + kb);                            \
    } while (0)

#define STORES(buf) do {                                             \
        uint32_t* as_ = As[buf];                                     \
        uint32_t* bs_ = Bs[buf];                                     \
        uint2 aw0, aw1;                                              \
        aw0.x = packbf(ra0.x, ra0.y); aw0.y = packbf(ra0.z, ra0.w);  \
        aw1.x = packbf(ra1.x, ra1.y); aw1.y = packbf(ra1.z, ra1.w);  \
        *(uint2*)(as_ + a_row * A_WSTR + (a_c4 >> 1)) = aw0;         \
        *(uint2*)(as_ + (a_row + 64) * A_WSTR + (a_c4 >> 1)) = aw1;  \
        uint4 bw;                                                    \
        bw.x = packbf(rb0.x, rb1.x); bw.y = packbf(rb0.y, rb1.y);    \
        bw.z = packbf(rb0.z, rb1.z); bw.w = packbf(rb0.w, rb1.w);    \
        *(uint4*)(bs_ + b_p * B_WSTR + b_c4) = bw;                   \
    } while (0)

    const int NT = K >> 4;

    LOADG(0);
    STORES(0);
    __syncthreads();

    for (int t = 0; t < NT; t++) {
        const int cur = t & 1;
        if (t + 1 < NT) LOADG(t + 1);

        const uint32_t* as_ = As[cur];
        const uint32_t* bs_ = Bs[cur];

        unsigned af[4][4], bf2[4][2];
#pragma unroll
        for (int mt = 0; mt < 4; mt++) {
            const uint32_t* ap = as_ + (wm + mt * 16 + g) * A_WSTR + tg;
            af[mt][0] = ap[0];
            af[mt][1] = ap[8 * A_WSTR];
            af[mt][2] = ap[4];
            af[mt][3] = ap[8 * A_WSTR + 4];
        }
#pragma unroll
        for (int nt = 0; nt < 4; nt++) {
            const int col = wn + nt * 8 + g;
            bf2[nt][0] = bs_[tg * B_WSTR + col];
            bf2[nt][1] = bs_[(tg + 4) * B_WSTR + col];
        }
#pragma unroll
        for (int mt = 0; mt < 4; mt++)
#pragma unroll
            for (int nt = 0; nt < 4; nt++)
                MMA_BF16(acc[mt][nt], af[mt], bf2[nt][0], bf2[nt][1]);

        if (t + 1 < NT) STORES((t + 1) & 1);
        __syncthreads();
    }

#pragma unroll
    for (int mt = 0; mt < 4; mt++) {
        const int row0 = bm + wm + mt * 16 + g;
#pragma unroll
        for (int nt = 0; nt < 4; nt++) {
            const int col = bn + wn + nt * 8 + tg * 2;
            const float bv0 = bias[col], bv1 = bias[col + 1];
            const uint32_t w0 = packh((acc[mt][nt][0] + bv0) * sc,
                                      (acc[mt][nt][1] + bv1) * sc);
            const uint32_t w1 = packh((acc[mt][nt][2] + bv0) * sc,
                                      (acc[mt][nt][3] + bv1) * sc);
            *(uint32_t*)(C16 + (size_t)row0 * N + col)       = w0;
            *(uint32_t*)(C16 + (size_t)(row0 + 8) * N + col) = w1;
        }
    }
#undef LOADG
#undef STORES
}

// ----------------------------------------------------------------------------
// fp16 flash attention (R15-validated math), K/V staging double-buffered
// via cp.async so tile loads overlap the previous tile's mma stream.
// ----------------------------------------------------------------------------
#define HSTR 72            // halves per smem row (64 + 8 pad)

template<bool CAUSAL>
__global__ __launch_bounds__(128) void attn_fp16(
    const uint16_t* __restrict__ Q, const uint16_t* __restrict__ K,
    const uint16_t* __restrict__ V, float* __restrict__ O)
{
    __shared__ __align__(16) uint16_t sQ[64 * HSTR];
    __shared__ __align__(16) uint16_t sK[2][64 * HSTR];
    __shared__ __align__(16) uint16_t sV[2][64 * HSTR];
    uint32_t* sQw = (uint32_t*)sQ;     // word stride 36

    const int b  = blockIdx.z;
    const int h  = blockIdx.y;
    const int q0 = blockIdx.x * 64;
    const int tid  = threadIdx.x;
    const int lane = tid & 31;
    const int w    = tid >> 5;
    const int g    = lane >> 2;
    const int tg   = lane & 3;
    const size_t hoff = ((size_t)(b * NHEADS + h)) * SEQ * HDIM;
    const uint32_t sKbase0 = smem_u32(sK[0]);
    const uint32_t sKbase1 = smem_u32(sK[1]);
    const uint32_t sVbase0 = smem_u32(sV[0]);
    const uint32_t sVbase1 = smem_u32(sV[1]);

    const int ntiles = CAUSAL ? (q0 / 64 + 1) : (SEQ / 64);

    // ---- stage issue: cp.async 16B chunks for K+V of one tile ----
#define ISSUE_KV(stage) do {                                                  \
        const int js = ((stage) < ntiles ? (stage) : ntiles - 1) * 64;        \
        const int bsel = (stage) & 1;                                         \
        const uint32_t kb_ = bsel ? sKbase1 : sKbase0;                        \
        const uint32_t vb_ = bsel ? sVbase1 : sVbase0;                        \
        _Pragma("unroll")                                                     \
        for (int i = 0; i < 4; i++) {                                         \
            const int idx = tid + i * 128;                                    \
            const int row = idx >> 3;                                         \
            const int c8  = idx & 7;                                          \
            const size_t gaddr = hoff + (size_t)(js + row) * HDIM + c8 * 8;   \
            const uint32_t soff = (uint32_t)(row * HSTR + c8 * 8) * 2;        \
            cp_async16(kb_ + soff, K + gaddr);                                \
            cp_async16(vb_ + soff, V + gaddr);                                \
        }                                                                     \
        CP_COMMIT();                                                          \
    } while (0)

    // ---- stage Q (plain copies) + prologue KV issues ----
    ISSUE_KV(0);
    ISSUE_KV(1);
#pragma unroll
    for (int i = 0; i < 4; i++) {
        const int idx = tid + i * 128;
        const int row = idx >> 3;
        const int c8  = idx & 7;
        uint4 qv = *(const uint4*)(Q + hoff + (size_t)(q0 + row) * HDIM + c8 * 8);
        *(uint4*)(sQw + row * 36 + c8 * 4) = qv;
    }
    __syncthreads();

    // ---- Q fragments (register resident); rows = w*16 + {g, g+8} ----
    uint32_t aQ[4][4];
#pragma unroll
    for (int kk = 0; kk < 4; kk++) {
        const uint32_t* qb = sQw + (w * 16 + g) * 36 + kk * 8 + tg;
        aQ[kk][0] = qb[0];
        aQ[kk][1] = qb[8 * 36];
        aQ[kk][2] = qb[4];
        aQ[kk][3] = qb[8 * 36 + 4];
    }

    float cO[8][4];
#pragma unroll
    for (int nt = 0; nt < 8; nt++)
#pragma unroll
        for (int r = 0; r < 4; r++) cO[nt][r] = 0.f;
    float lrow[2] = { 0.f, 0.f };

    // ldmatrix lane decomposition (shared by K and V fragment loads)
    const int mat = lane >> 3;      // 0..3
    const int mr  = lane & 7;       // 0..7

    for (int t = 0; t < ntiles; t++) {
        const int j0 = t * 64;
        const int bsel = t & 1;
        const uint32_t sKbase = bsel ? sKbase1 : sKbase0;
        const uint32_t sVbase = bsel ? sVbase1 : sVbase0;

        if (t + 2 < ntiles) CP_WAIT(1);
        else                CP_WAIT(0);
        __syncthreads();

        // ---- S = Q @ K^T : K B-frags via ldmatrix.x4 (non-trans) ----
        float cS[8][4];
#pragma unroll
        for (int nt = 0; nt < 8; nt++)
#pragma unroll
            for (int r = 0; r < 4; r++) cS[nt][r] = 0.f;

#pragma unroll
        for (int kk = 0; kk < 4; kk++)
#pragma unroll
            for (int ntp = 0; ntp < 4; ntp++) {
                const int key = (ntp * 2 + (mat >> 1)) * 8 + mr;
                const int dcl = kk * 16 + (mat & 1) * 8;
                const uint32_t addr = sKbase + (uint32_t)(key * HSTR + dcl) * 2;
                uint32_t b0, b1, b2, b3;
                LDSM_X4(b0, b1, b2, b3, addr);
                MMA_F16(cS[2 * ntp],     aQ[kk], b0, b1);
                MMA_F16(cS[2 * ntp + 1], aQ[kk], b2, b3);
            }

        // ---- causal mask (diagonal tile only) ----
        if (CAUSAL && t == ntiles - 1) {
            const int rbase = q0 + w * 16 + g;
#pragma unroll
            for (int nt = 0; nt < 8; nt++) {
                const int c0 = j0 + nt * 8 + tg * 2;
                if (c0     > rbase)     cS[nt][0] = -1e30f;
                if (c0 + 1 > rbase)     cS[nt][1] = -1e30f;
                if (c0     > rbase + 8) cS[nt][2] = -1e30f;
                if (c0 + 1 > rbase + 8) cS[nt][3] = -1e30f;
            }
        }

        // ---- p = 2^S, packed f16x2 (these ARE the PV A-frag words) ----
        uint32_t plo[8], phi[8];
#pragma unroll
        for (int nt = 0; nt < 8; nt++) {
            plo[nt] = ex2h2(packh(cS[nt][0], cS[nt][1]));
            phi[nt] = ex2h2(packh(cS[nt][2], cS[nt][3]));
        }

        uint32_t aP[4][4];
#pragma unroll
        for (int kk = 0; kk < 4; kk++) {
            aP[kk][0] = plo[2 * kk];
            aP[kk][1] = phi[2 * kk];
            aP[kk][2] = plo[2 * kk + 1];
            aP[kk][3] = phi[2 * kk + 1];
        }

        // ---- row sums via mma with B = ones (fp32 accumulate) ----
        {
            float cSum[4] = { 0.f, 0.f, 0.f, 0.f };
#pragma unroll
            for (int kk = 0; kk < 4; kk++)
                MMA_F16(cSum, aP[kk], 0x3C003C00u, 0x3C003C00u);
            lrow[0] += cSum[0];
            lrow[1] += cSum[2];
        }

        // ---- O += P @ V : V B-frags via ldmatrix.x4.trans ----
#pragma unroll
        for (int kk = 0; kk < 4; kk++)
#pragma unroll
            for (int np = 0; np < 4; np++) {
                const int key = kk * 16 + (mat & 1) * 8 + mr;
                const int dcl = np * 16 + (mat >> 1) * 8;
                const uint32_t addr = sVbase + (uint32_t)(key * HSTR + dcl) * 2;
                uint32_t v0, v1, v2, v3;
                LDSM_X4_TRANS(v0, v1, v2, v3, addr);
                MMA_F16(cO[2 * np],     aP[kk], v0, v1);
                MMA_F16(cO[2 * np + 1], aP[kk], v2, v3);
            }

        __syncthreads();           // all warps done with buffer t&1
        if (t + 2 < ntiles) ISSUE_KV(t + 2);
    }

    // ---- epilogue: normalize and store (folds head transpose) ----
    const float inv0 = 1.f / lrow[0];
    const float inv1 = 1.f / lrow[1];
    const int r0 = q0 + w * 16 + g;
    float* o0p = O + (size_t)(b * SEQ + r0) * DMODEL + h * HDIM;
    float* o1p = O + (size_t)(b * SEQ + r0 + 8) * DMODEL + h * HDIM;
#pragma unroll
    for (int nt = 0; nt < 8; nt++) {
        const int c = nt * 8 + tg * 2;
        float2 v0, v1;
        v0.x = cO[nt][0] * inv0; v0.y = cO[nt][1] * inv0;
        v1.x = cO[nt][2] * inv1; v1.y = cO[nt][3] * inv1;
        *(float2*)(o0p + c) = v0;
        *(float2*)(o1p + c) = v1;
    }
#undef ISSUE_KV
}

// ----------------------------------------------------------------------------
// LayerNorm (unchanged)
// ----------------------------------------------------------------------------
__global__ __launch_bounds__(256) void ln_kernel(
    const float* __restrict__ X, const float* __restrict__ g,
    const float* __restrict__ bb, float* __restrict__ Y)
{
    __shared__ float red[16];
    const int row = blockIdx.x;
    const int tid = threadIdx.x;
    const float4 xv = *(const float4*)(X + (size_t)row * DMODEL + tid * 4);

    float s  = xv.x + xv.y + xv.z + xv.w;
    float sq = xv.x*xv.x + xv.y*xv.y + xv.z*xv.z + xv.w*xv.w;
#pragma unroll
    for (int off = 16; off > 0; off >>= 1) {
        s  += __shfl_xor_sync(0xffffffffu, s,  off);
        sq += __shfl_xor_sync(0xffffffffu, sq, off);
    }
    const int warp = tid >> 5, lane = tid & 31;
    if (lane == 0) { red[warp] = s; red[warp + 8] = sq; }
    __syncthreads();
    if (warp == 0) {
        float a = (lane < 8) ? red[lane] : 0.f;
        float c = (lane < 8) ? red[lane + 8] : 0.f;
#pragma unroll
        for (int off = 4; off > 0; off >>= 1) {
            a += __shfl_xor_sync(0xffffffffu, a, off);
            c += __shfl_xor_sync(0xffffffffu, c, off);
        }
        if (lane == 0) { red[0] = a; red[1] = c; }
    }
    __syncthreads();
    const float mu  = red[0] * (1.f / DMODEL);
    const float var = red[1] * (1.f / DMODEL) - mu * mu;
    const float rstd = rsqrtf(var + LN_EPS);

    const float4 gv = *(const float4*)(g  + tid * 4);
    const float4 bv = *(const float4*)(bb + tid * 4);
    float4 yv;
    yv.x = (xv.x - mu) * rstd * gv.x + bv.x;
    yv.y = (xv.y - mu) * rstd * gv.y + bv.y;
    yv.z = (xv.z - mu) * rstd * gv.z + bv.z;
    yv.w = (xv.w - mu) * rstd * gv.w + bv.w;
    *(float4*)(Y + (size_t)row * DMODEL + tid * 4) = yv;
}

// ----------------------------------------------------------------------------
// Launch
// ----------------------------------------------------------------------------
extern "C" void kernel_launch(void* const* d_in, const int* in_sizes, int n_in,
                              void* d_out, int out_size)
{
    const float* x    = (const float*)d_in[0];
    const float* enc  = (const float*)d_in[1];
    const float* s_wq = (const float*)d_in[2];  const float* s_bq = (const float*)d_in[3];
    const float* s_wk = (const float*)d_in[4];  const float* s_bk = (const float*)d_in[5];
    const float* s_wv = (const float*)d_in[6];  const float* s_bv = (const float*)d_in[7];
    const float* s_wo = (const float*)d_in[8];  const float* s_bo = (const float*)d_in[9];
    const float* c_wq = (const float*)d_in[10]; const float* c_bq = (const float*)d_in[11];
    const float* c_wk = (const float*)d_in[12]; const float* c_bk = (const float*)d_in[13];
    const float* c_wv = (const float*)d_in[14]; const float* c_bv = (const float*)d_in[15];
    const float* c_wo = (const float*)d_in[16]; const float* c_bo = (const float*)d_in[17];
    const float* f_w1 = (const float*)d_in[18]; const float* f_b1 = (const float*)d_in[19];
    const float* f_w2 = (const float*)d_in[20]; const float* f_b2 = (const float*)d_in[21];
    const float* ln1g = (const float*)d_in[22]; const float* ln1b = (const float*)d_in[23];
    const float* ln2g = (const float*)d_in[24]; const float* ln2b = (const float*)d_in[25];
    const float* ln3g = (const float*)d_in[26]; const float* ln3b = (const float*)d_in[27];
    float* out = (float*)d_out;

    uint16_t *q, *k, *v;
    float *attn, *tmp, *y1, *y2, *ffn;
    cudaGetSymbolAddress((void**)&q,    h_q);
    cudaGetSymbolAddress((void**)&k,    h_k);
    cudaGetSymbolAddress((void**)&v,    h_v);
    cudaGetSymbolAddress((void**)&attn, g_attn);
    cudaGetSymbolAddress((void**)&tmp,  g_tmp);
    cudaGetSymbolAddress((void**)&y1,   g_y1);
    cudaGetSymbolAddress((void**)&y2,   g_y2);
    cudaGetSymbolAddress((void**)&ffn,  g_ffn);

    const dim3 blk(256);
    const dim3 ablk(128);
    const dim3 gatt(SEQ / 64, NHEADS, BATCH);
    const dim3 gln(TOK);

    GemmArgs ga;
    GemmH16Args gh;

    // ---- self attention: fused QKV projection -> fp16 (z=3) ----
    gh = GemmH16Args{};
    gh.A[0] = x;    gh.A[1] = x;    gh.A[2] = x;
    gh.W[0] = s_wq; gh.W[1] = s_wk; gh.W[2] = s_wv;
    gh.bias[0] = s_bq; gh.bias[1] = s_bk; gh.bias[2] = s_bv;
    gh.C[0] = q; gh.C[1] = k; gh.C[2] = v;
    gh.scale[0] = QSCALE; gh.scale[1] = 1.f; gh.scale[2] = 1.f;
    gh.N = DMODEL; gh.K = DMODEL;
    gemm_h16<<<dim3(DMODEL/128, TOK/128, 3), blk>>>(gh);

    attn_fp16<true><<<gatt, ablk>>>(q, k, v, attn);

    ga = GemmArgs{};
    ga.A[0] = attn; ga.W[0] = s_wo; ga.bias[0] = s_bo; ga.R[0] = x; ga.C[0] = tmp;
    ga.N = DMODEL; ga.K = DMODEL;
    gemm_bf16<false,true><<<dim3(DMODEL/128, TOK/128, 1), blk>>>(ga);
    ln_kernel<<<gln, blk>>>(tmp, ln1g, ln1b, y1);

    // ---- cross attention: fused Q(y1) + K,V(enc) projection -> fp16 ----
    gh.A[0] = y1;   gh.A[1] = enc;  gh.A[2] = enc;
    gh.W[0] = c_wq; gh.W[1] = c_wk; gh.W[2] = c_wv;
    gh.bias[0] = c_bq; gh.bias[1] = c_bk; gh.bias[2] = c_bv;
    gh.C[0] = q; gh.C[1] = k; gh.C[2] = v;
    gemm_h16<<<dim3(DMODEL/128, TOK/128, 3), blk>>>(gh);

    attn_fp16<false><<<gatt, ablk>>>(q, k, v, attn);

    ga.A[0] = attn; ga.W[0] = c_wo; ga.bias[0] = c_bo; ga.R[0] = y1; ga.C[0] = tmp;
    gemm_bf16<false,true><<<dim3(DMODEL/128, TOK/128, 1), blk>>>(ga);
    ln_kernel<<<gln, blk>>>(tmp, ln2g, ln2b, y2);

    // ---- FFN ----
    ga.A[0] = y2; ga.W[0] = f_w1; ga.bias[0] = f_b1; ga.R[0] = x; ga.C[0] = ffn;
    ga.N = DFF; ga.K = DMODEL;
    gemm_bf16<true,false><<<dim3(DFF/128, TOK/128, 1), blk>>>(ga);

    ga.A[0] = ffn; ga.W[0] = f_w2; ga.bias[0] = f_b2; ga.R[0] = y2; ga.C[0] = tmp;
    ga.N = DMODEL; ga.K = DFF;
    gemm_bf16<false,true><<<dim3(DMODEL/128, TOK/128, 1), blk>>>(ga);
    ln_kernel<<<gln, blk>>>(tmp, ln3g, ln3b, out);
}